// round 15
// baseline (speedup 1.0000x reference)
#include <cuda_runtime.h>
#include <cuda_bf16.h>
#include <stdint.h>
#include <math.h>

#define BB 2
#define SS 1024
#define DD 256
#define HH 4
#define CC 64
#define WINSZ 10
#define NITER 2
#define MM 2048
#define HID 2048
#define BSD (BB*SS*DD)
#define MH ((size_t)MM*HID)
#define MD ((size_t)MM*DD)

typedef __nv_bfloat16 bf16;

// ---------------- scratch (device globals; no allocation) -------------------
__device__ float g_Q[3*BSD], g_Kb[3*BSD], g_Vb[3*BSD], g_Gb[3*BSD];
__device__ float g_b56[DD];
__device__ float g_part[24*MD];
__device__ bf16 g_lnh[7*BSD], g_lnl[7*BSD];
__device__ bf16 g_cth[3*BSD], g_ctl[3*BSD];
__device__ bf16 g_hidh[3*MH], g_hidl[3*MH];

__device__ bf16 g_WqTh[7*DD*DD], g_WqTl[7*DD*DD];
__device__ bf16 g_WkTh[7*DD*DD], g_WkTl[7*DD*DD];
__device__ bf16 g_WvTh[7*DD*DD], g_WvTl[7*DD*DD];
__device__ bf16 g_GwTh[7*DD*DD], g_GwTl[7*DD*DD];
__device__ bf16 g_OwTh[7*DD*DD], g_OwTl[7*DD*DD];
__device__ bf16 g_w1Th[(size_t)6*DD*HID], g_w1Tl[(size_t)6*DD*HID];
__device__ bf16 g_w2Th[(size_t)6*HID*DD], g_w2Tl[(size_t)6*HID*DD];

__device__ __forceinline__ void split2(float v, bf16& h, bf16& l){
    h = __float2bfloat16(v);
    l = __float2bfloat16(v - __bfloat162float(h));
}
__device__ __forceinline__ uint32_t smem_u32(const void* p){
    uint32_t a;
    asm("{ .reg .u64 t; cvta.to.shared.u64 t, %1; cvt.u32.u64 %0, t; }" : "=r"(a) : "l"(p));
    return a;
}
__device__ __forceinline__ void cp16(uint32_t saddr, const void* g){
    asm volatile("cp.async.cg.shared.global [%0], [%1], 16;" :: "r"(saddr), "l"(g));
}
__device__ __forceinline__ void ldsm_x4(uint32_t* r, uint32_t addr){
    asm volatile("ldmatrix.sync.aligned.m8n8.x4.shared.b16 {%0,%1,%2,%3}, [%4];"
        : "=r"(r[0]), "=r"(r[1]), "=r"(r[2]), "=r"(r[3]) : "r"(addr));
}
__device__ __forceinline__ float warp_sum(float s){
    #pragma unroll
    for (int o = 16; o > 0; o >>= 1) s += __shfl_xor_sync(0xffffffffu, s, o);
    return s;
}
__device__ __forceinline__ void store8(bf16* oh, bf16* ol, size_t base, const float* v){
    __align__(16) bf16 h[8], l[8];
    #pragma unroll
    for (int i = 0; i < 8; i++) split2(v[i], h[i], l[i]);
    *(uint4*)&oh[base] = *(const uint4*)h;
    *(uint4*)&ol[base] = *(const uint4*)l;
}

// ---------------- weight transpose + split ----------------------------------
__device__ __forceinline__ void wsplit_body(
    const float* w, bf16* th, bf16* tl, int N, int ldt)
{
    __shared__ float sm[32][33];
    int n0 = blockIdx.x * 32, k0 = blockIdx.y * 32;
    int tx = threadIdx.x & 31, ty = threadIdx.x >> 5;
    #pragma unroll
    for (int i = 0; i < 4; i++)
        sm[ty + i*8][tx] = w[(size_t)(k0 + ty + i*8) * N + n0 + tx];
    __syncthreads();
    #pragma unroll
    for (int i = 0; i < 4; i++) {
        int n = n0 + ty + i*8;
        bf16 h, l; split2(sm[tx][ty + i*8], h, l);
        th[(size_t)n * ldt + k0 + tx] = h;
        tl[(size_t)n * ldt + k0 + tx] = l;
    }
}

struct WsAll { const float* src[5]; bf16* th[5]; bf16* tl[5]; const float* aOb; };
__global__ void __launch_bounds__(256) wsplit_all(WsAll wa)
{
    if (blockIdx.z == 35) {
        if (blockIdx.x == 0 && blockIdx.y == 0 && threadIdx.x < DD)
            g_b56[threadIdx.x] = wa.aOb[5*DD + threadIdx.x] + wa.aOb[6*DD + threadIdx.x];
        return;
    }
    int fam = blockIdx.z / 7, mod = blockIdx.z % 7;
    wsplit_body(wa.src[fam] + (size_t)mod*DD*DD,
                wa.th[fam] + (size_t)mod*DD*DD, wa.tl[fam] + (size_t)mod*DD*DD,
                DD, DD);
}
// merged w1+w2 split: z 0..5 -> ff_w1 module z; z 6..11 -> ff_w2 module z-6
__global__ void __launch_bounds__(256) wsplit_merged(
    const float* __restrict__ W1, const float* __restrict__ W2)
{
    int z = blockIdx.z;
    void* pa;
    if (z < 6) {
        if (blockIdx.y >= 8) return;
        wsplit_body(W1 + (size_t)z*DD*HID,
                    g_w1Th + (size_t)z*DD*HID, g_w1Tl + (size_t)z*DD*HID,
                    HID, DD);
    } else {
        if (blockIdx.x >= 8) return;
        int m = z - 6;
        wsplit_body(W2 + (size_t)m*HID*DD,
                    g_w2Th + (size_t)m*HID*DD, g_w2Tl + (size_t)m*HID*DD,
                    DD, HID);
    }
    (void)pa;
}

// ---------------- warp-per-row LayerNorm (batched over z) -------------------
struct LnS { const float* x; const float* g; const float* b; bf16* oh; bf16* ol; };
struct LnBatch { LnS s[3]; };

__global__ void __launch_bounds__(256) ln_kernel(LnBatch lb)
{
    LnS sl = lb.s[blockIdx.y];
    int wid = threadIdx.x >> 5, lane = threadIdx.x & 31;
    int row = blockIdx.x * 8 + wid;
    size_t base = (size_t)row * DD + lane * 8;

    float v[8];
    float4 p0 = *(const float4*)&sl.x[base];
    float4 p1 = *(const float4*)&sl.x[base + 4];
    v[0]=p0.x; v[1]=p0.y; v[2]=p0.z; v[3]=p0.w;
    v[4]=p1.x; v[5]=p1.y; v[6]=p1.z; v[7]=p1.w;

    float s = 0.f;
    #pragma unroll
    for (int i = 0; i < 8; i++) s += v[i];
    float mean = warp_sum(s) * (1.0f/DD);
    float q = 0.f;
    #pragma unroll
    for (int i = 0; i < 8; i++) { float d = v[i]-mean; q += d*d; }
    float rstd = rsqrtf(warp_sum(q) * (1.0f/DD) + 1e-5f);

    int c = lane * 8;
    float4 g0 = *(const float4*)&sl.g[c], g1 = *(const float4*)&sl.g[c+4];
    float4 b0 = *(const float4*)&sl.b[c], b1 = *(const float4*)&sl.b[c+4];
    float gg[8] = {g0.x,g0.y,g0.z,g0.w,g1.x,g1.y,g1.z,g1.w};
    float bb[8] = {b0.x,b0.y,b0.z,b0.w,b1.x,b1.y,b1.z,b1.w};
    float out[8];
    #pragma unroll
    for (int i = 0; i < 8; i++) out[i] = (v[i]-mean)*rstd*gg[i] + bb[i];
    store8(sl.oh, sl.ol, base, out);
}

// ---------------- fused split-K reduce + LN(s), warp-per-row ----------------
struct FRdS {
    const float* p; const float* bias; const float* res; float* dst; int nsplit;
    int nln;
    const float *lg0, *lb0; bf16 *oh0, *ol0;
    const float *lg1, *lb1; bf16 *oh1, *ol1;
};
struct FRdBatch { FRdS s[3]; };

__global__ void __launch_bounds__(256) fused_reduce_ln(FRdBatch rb)
{
    FRdS sl = rb.s[blockIdx.y];
    int wid = threadIdx.x >> 5, lane = threadIdx.x & 31;
    int row = blockIdx.x * 8 + wid;
    size_t base = (size_t)row * DD + lane * 8;
    int c = lane * 8;

    float a[8];
    {
        float4 p0 = *(const float4*)&sl.p[base];
        float4 p1 = *(const float4*)&sl.p[base + 4];
        a[0]=p0.x; a[1]=p0.y; a[2]=p0.z; a[3]=p0.w;
        a[4]=p1.x; a[5]=p1.y; a[6]=p1.z; a[7]=p1.w;
    }
    for (int s = 1; s < sl.nsplit; s++) {
        float4 p0 = *(const float4*)&sl.p[(size_t)s*MD + base];
        float4 p1 = *(const float4*)&sl.p[(size_t)s*MD + base + 4];
        a[0]+=p0.x; a[1]+=p0.y; a[2]+=p0.z; a[3]+=p0.w;
        a[4]+=p1.x; a[5]+=p1.y; a[6]+=p1.z; a[7]+=p1.w;
    }
    {
        float4 b0 = *(const float4*)&sl.bias[c], b1 = *(const float4*)&sl.bias[c+4];
        a[0]+=b0.x; a[1]+=b0.y; a[2]+=b0.z; a[3]+=b0.w;
        a[4]+=b1.x; a[5]+=b1.y; a[6]+=b1.z; a[7]+=b1.w;
    }
    if (sl.res) {
        float4 r0 = *(const float4*)&sl.res[base], r1 = *(const float4*)&sl.res[base+4];
        a[0]+=r0.x; a[1]+=r0.y; a[2]+=r0.z; a[3]+=r0.w;
        a[4]+=r1.x; a[5]+=r1.y; a[6]+=r1.z; a[7]+=r1.w;
    }
    {
        float4 o0 = make_float4(a[0],a[1],a[2],a[3]);
        float4 o1 = make_float4(a[4],a[5],a[6],a[7]);
        *(float4*)&sl.dst[base] = o0;
        *(float4*)&sl.dst[base+4] = o1;
    }

    float s = 0.f;
    #pragma unroll
    for (int i = 0; i < 8; i++) s += a[i];
    float mean = warp_sum(s) * (1.0f/DD);
    float q = 0.f;
    #pragma unroll
    for (int i = 0; i < 8; i++) { float d = a[i]-mean; q += d*d; }
    float rstd = rsqrtf(warp_sum(q) * (1.0f/DD) + 1e-5f);

    float nrm[8];
    #pragma unroll
    for (int i = 0; i < 8; i++) nrm[i] = (a[i]-mean)*rstd;

    {
        float4 g0 = *(const float4*)&sl.lg0[c], g1 = *(const float4*)&sl.lg0[c+4];
        float4 b0 = *(const float4*)&sl.lb0[c], b1 = *(const float4*)&sl.lb0[c+4];
        float gg[8] = {g0.x,g0.y,g0.z,g0.w,g1.x,g1.y,g1.z,g1.w};
        float bb[8] = {b0.x,b0.y,b0.z,b0.w,b1.x,b1.y,b1.z,b1.w};
        float out[8];
        #pragma unroll
        for (int i = 0; i < 8; i++) out[i] = nrm[i]*gg[i] + bb[i];
        store8(sl.oh0, sl.ol0, base, out);
    }
    if (sl.nln > 1) {
        float4 g0 = *(const float4*)&sl.lg1[c], g1 = *(const float4*)&sl.lg1[c+4];
        float4 b0 = *(const float4*)&sl.lb1[c], b1 = *(const float4*)&sl.lb1[c+4];
        float gg[8] = {g0.x,g0.y,g0.z,g0.w,g1.x,g1.y,g1.z,g1.w};
        float bb[8] = {b0.x,b0.y,b0.z,b0.w,b1.x,b1.y,b1.z,b1.w};
        float out[8];
        #pragma unroll
        for (int i = 0; i < 8; i++) out[i] = nrm[i]*gg[i] + bb[i];
        store8(sl.oh1, sl.ol1, base, out);
    }
}

// ---------------- batched split-compensated MMA GEMM ------------------------
struct Slice {
    const bf16 *Ah, *Al, *Bh, *Bl;
    const float *bias, *res;
    float* C; bf16 *Ch, *Cl;
    int mode, lda, ldb, Ksub;
};
struct Batch { Slice s[24]; };

#define BKC 32
#define LDSB 40
#define ARRE (128*LDSB)
#define STGE (4*ARRE)
#define GSMEM (2*STGE*2)

__device__ __forceinline__ void mma16816(float* c, const uint32_t* a, const uint32_t* b){
    asm volatile("mma.sync.aligned.m16n8k16.row.col.f32.bf16.bf16.f32 "
        "{%0,%1,%2,%3}, {%4,%5,%6,%7}, {%8,%9}, {%0,%1,%2,%3};"
        : "+f"(c[0]), "+f"(c[1]), "+f"(c[2]), "+f"(c[3])
        : "r"(a[0]), "r"(a[1]), "r"(a[2]), "r"(a[3]), "r"(b[0]), "r"(b[1]));
}

__global__ void __launch_bounds__(256,2)
gemm_batched(Batch bt, int M, int N)
{
    extern __shared__ __align__(16) bf16 smem[];
    const Slice sl = bt.s[blockIdx.z];
    const int tid  = threadIdx.x;
    const int warp = tid >> 5, lane = tid & 31;
    const int wm = warp >> 2, wn = warp & 3;
    const int row0 = blockIdx.y * 128, col0 = blockIdx.x * 128;
    const int g8 = lane >> 2, tig = lane & 3;
    const uint32_t sb = smem_u32(smem);
    const int NC = sl.Ksub / BKC;
    const int lda = sl.lda, ldb = sl.ldb;

    float acc[4][4][4];
    #pragma unroll
    for (int i=0;i<4;i++) for (int j=0;j<4;j++) for (int q=0;q<4;q++) acc[i][j][q]=0.f;

    const int ck0 = tid, ck1 = tid + 256;
    const int r0c = ck0 >> 2, c0c = (ck0 & 3) * 8;
    const int r1c = ck1 >> 2, c1c = (ck1 & 3) * 8;

    const int lmat = lane >> 3, lrow = lane & 7;
    const uint32_t a_lane_off = (uint32_t)(((lmat & 1) * 8 + lrow) * LDSB + (lmat >> 1) * 8) * 2;
    const uint32_t b_lane_off = (uint32_t)(((lmat >> 1) * 8 + lrow) * LDSB + (lmat & 1) * 8) * 2;

    auto cpStage = [&](int c, int st){
        int kc = c * BKC;
        uint32_t base = sb + (uint32_t)(st * STGE) * 2;
        uint32_t so0 = (uint32_t)(r0c * LDSB + c0c) * 2;
        uint32_t so1 = (uint32_t)(r1c * LDSB + c1c) * 2;
        cp16(base + so0,            sl.Ah + (size_t)(row0 + r0c) * lda + kc + c0c);
        cp16(base + so1,            sl.Ah + (size_t)(row0 + r1c) * lda + kc + c1c);
        cp16(base + ARRE*2 + so0,   sl.Al + (size_t)(row0 + r0c) * lda + kc + c0c);
        cp16(base + ARRE*2 + so1,   sl.Al + (size_t)(row0 + r1c) * lda + kc + c1c);
        cp16(base + ARRE*4 + so0,   sl.Bh + (size_t)(col0 + r0c) * ldb + kc + c0c);
        cp16(base + ARRE*4 + so1,   sl.Bh + (size_t)(col0 + r1c) * ldb + kc + c1c);
        cp16(base + ARRE*6 + so0,   sl.Bl + (size_t)(col0 + r0c) * ldb + kc + c0c);
        cp16(base + ARRE*6 + so1,   sl.Bl + (size_t)(col0 + r1c) * ldb + kc + c1c);
        asm volatile("cp.async.commit_group;" ::: "memory");
    };

    cpStage(0, 0);
    if (NC > 1) cpStage(1, 1);
    else asm volatile("cp.async.commit_group;" ::: "memory");

    for (int c = 0; c < NC; c++) {
        const int st = c & 1;
        if (c + 2 < NC) asm volatile("cp.async.wait_group 1;" ::: "memory");
        else            asm volatile("cp.async.wait_group 0;" ::: "memory");
        __syncthreads();

        const uint32_t sA_h = sb + (uint32_t)(st*STGE) * 2;
        const uint32_t sA_l = sA_h + ARRE*2;
        const uint32_t sB_h = sA_h + ARRE*4;
        const uint32_t sB_l = sA_h + ARRE*6;

        #pragma unroll
        for (int kk = 0; kk < 2; kk++) {
            const uint32_t kbo = (uint32_t)(kk * 16) * 2;
            uint32_t bh[4][2], bl[4][2];
            #pragma unroll
            for (int pr = 0; pr < 2; pr++) {
                uint32_t nbase = (uint32_t)((wn*32 + pr*16) * LDSB) * 2;
                uint32_t r4[4];
                ldsm_x4(r4, sB_h + nbase + kbo + b_lane_off);
                bh[pr*2][0] = r4[0]; bh[pr*2][1] = r4[1];
                bh[pr*2+1][0] = r4[2]; bh[pr*2+1][1] = r4[3];
                ldsm_x4(r4, sB_l + nbase + kbo + b_lane_off);
                bl[pr*2][0] = r4[0]; bl[pr*2][1] = r4[1];
                bl[pr*2+1][0] = r4[2]; bl[pr*2+1][1] = r4[3];
            }
            #pragma unroll
            for (int mi = 0; mi < 4; mi++) {
                uint32_t rbase = (uint32_t)((wm*64 + mi*16) * LDSB) * 2;
                uint32_t ah[4], al[4];
                ldsm_x4(ah, sA_h + rbase + kbo + a_lane_off);
                ldsm_x4(al, sA_l + rbase + kbo + a_lane_off);
                #pragma unroll
                for (int ni = 0; ni < 4; ni++) {
                    mma16816(acc[mi][ni], ah, bh[ni]);
                    mma16816(acc[mi][ni], ah, bl[ni]);
                    mma16816(acc[mi][ni], al, bh[ni]);
                }
            }
        }
        __syncthreads();
        if (c + 2 < NC) cpStage(c + 2, st);
    }

    #pragma unroll
    for (int mi = 0; mi < 4; mi++) {
        #pragma unroll
        for (int ni = 0; ni < 4; ni++) {
            int r1 = row0 + wm*64 + mi*16 + g8;
            int c1 = col0 + wn*32 + ni*8 + tig*2;
            #pragma unroll
            for (int q = 0; q < 4; q++) {
                int r = (q < 2) ? r1 : r1 + 8;
                int cc = c1 + (q & 1);
                float v = acc[mi][ni][q];
                if (sl.bias) v += sl.bias[cc];
                if (sl.mode == 1)      v = fmaxf(v, 0.f);
                else if (sl.mode == 2) v = 1.f / (1.f + __expf(-v));
                if (sl.Ch) {
                    bf16 h, l; split2(v, h, l);
                    sl.Ch[(size_t)r * N + cc] = h;
                    sl.Cl[(size_t)r * N + cc] = l;
                } else {
                    if (sl.res) v += sl.res[(size_t)r * N + cc];
                    sl.C[(size_t)r * N + cc] = v;
                }
            }
        }
    }
}

// ---------------- windowed attention core (batched over z) ------------------
struct AtS { const float* Q; const float* K; const float* V; const float* G;
             bf16* cth; bf16* ctl; };
struct AtBatch { AtS s[3]; };

__global__ void __launch_bounds__(256)
attn_core_kernel(AtBatch ab, const unsigned char* __restrict__ mask)
{
    AtS sl = ab.s[blockIdx.y];
    int idx  = blockIdx.x * blockDim.x + threadIdx.x;
    int gw   = idx >> 5;
    int lane = idx & 31;
    int s = gw & (SS - 1);
    int h = (gw >> 10) & (HH - 1);
    int n = gw >> 12;

    int base_q = (n * SS + s) * DD + h * CC;
    float q0 = sl.Q[base_q + lane];
    float q1 = sl.Q[base_q + 32 + lane];

    int t0 = s - WINSZ; if (t0 < 0) t0 = 0;
    int t1 = s + WINSZ; if (t1 > SS - 1) t1 = SS - 1;
    int cnt = t1 - t0 + 1;

    float sc[2 * WINSZ + 1];
    float mx = -1e30f;
    for (int i = 0; i < cnt; i++) {
        int t = t0 + i;
        float v;
        if (mask[n * SS + t]) v = -1e30f;
        else {
            int bk = (n * SS + t) * DD + h * CC;
            float p = q0 * sl.K[bk + lane] + q1 * sl.K[bk + 32 + lane];
            #pragma unroll
            for (int o = 16; o > 0; o >>= 1) p += __shfl_xor_sync(0xffffffffu, p, o);
            v = p * 0.125f;
        }
        sc[i] = v;
        mx = fmaxf(mx, v);
    }
    float denom = 0.f;
    for (int i = 0; i < cnt; i++) {
        float e = (sc[i] <= -1e29f) ? 0.f : __expf(sc[i] - mx);
        sc[i] = e; denom += e;
    }
    float inv = (denom > 0.f) ? (1.f / denom) : 0.f;
    float o0 = 0.f, o1 = 0.f;
    for (int i = 0; i < cnt; i++) {
        int bv = (n * SS + (t0 + i)) * DD + h * CC;
        float a = sc[i] * inv;
        o0 = fmaf(a, sl.V[bv + lane], o0);
        o1 = fmaf(a, sl.V[bv + 32 + lane], o1);
    }
    float v0 = o0 * sl.G[base_q + lane];
    float v1 = o1 * sl.G[base_q + 32 + lane];
    bf16 h0, l0, h1, l1;
    split2(v0, h0, l0); split2(v1, h1, l1);
    sl.cth[base_q + lane]      = h0;  sl.ctl[base_q + lane]      = l0;
    sl.cth[base_q + 32 + lane] = h1;  sl.ctl[base_q + 32 + lane] = l1;
}

// ---------------- host orchestration ----------------------------------------
extern "C" void kernel_launch(void* const* d_in, const int* in_sizes, int n_in,
                              void* d_out, int out_size)
{
    (void)in_sizes; (void)n_in; (void)out_size;
    const float* inL = (const float*)d_in[0];
    const float* inN = (const float*)d_in[1];
    const float* inO = (const float*)d_in[2];
    const unsigned char* mask = (const unsigned char*)d_in[3];
    const float* aWq = (const float*)d_in[4];
    const float* aWk = (const float*)d_in[5];
    const float* aWv = (const float*)d_in[6];
    const float* aGw = (const float*)d_in[7];
    const float* aGb = (const float*)d_in[8];
    const float* aOw = (const float*)d_in[9];
    const float* aOb = (const float*)d_in[10];
    const float* ln_g = (const float*)d_in[11];
    const float* ln_b = (const float*)d_in[12];
    const float* ff_g = (const float*)d_in[13];
    const float* ff_b = (const float*)d_in[14];
    const float* ff_w1 = (const float*)d_in[15];
    const float* ff_b1 = (const float*)d_in[16];
    const float* ff_w2 = (const float*)d_in[17];
    const float* ff_b2 = (const float*)d_in[18];

    float* L  = (float*)d_out;
    float* Nb = L + BSD;
    float* O  = Nb + BSD;
    float* X[3] = { L, Nb, O };

    cudaMemcpyAsync(L,  inL, (size_t)BSD * sizeof(float), cudaMemcpyDeviceToDevice);
    cudaMemcpyAsync(Nb, inN, (size_t)BSD * sizeof(float), cudaMemcpyDeviceToDevice);
    cudaMemcpyAsync(O,  inO, (size_t)BSD * sizeof(float), cudaMemcpyDeviceToDevice);

    void* pa;
    #define SYM(var, sym) cudaGetSymbolAddress(&pa, sym); auto var = (decltype(&sym[0]))pa;
    SYM(Qb, g_Q) SYM(Kb, g_Kb) SYM(Vb, g_Vb) SYM(Gg, g_Gb)
    SYM(lnh, g_lnh) SYM(lnl, g_lnl)
    SYM(cth, g_cth) SYM(ctl, g_ctl)
    SYM(hidh, g_hidh) SYM(hidl, g_hidl)
    SYM(b56, g_b56) SYM(part, g_part)
    SYM(wqh, g_WqTh) SYM(wql, g_WqTl) SYM(wkh, g_WkTh) SYM(wkl, g_WkTl)
    SYM(wvh, g_WvTh) SYM(wvl, g_WvTl) SYM(gwh, g_GwTh) SYM(gwl, g_GwTl)
    SYM(owh, g_OwTh) SYM(owl, g_OwTl)
    SYM(w1h, g_w1Th) SYM(w1l, g_w1Tl) SYM(w2h, g_w2Th) SYM(w2l, g_w2Tl)
    #undef SYM

    cudaFuncSetAttribute(gemm_batched, cudaFuncAttributeMaxDynamicSharedMemorySize, GSMEM);

    float* QKVG[4] = { Qb, Kb, Vb, Gg };
    auto LS = [&](int slot) { return lnh + (size_t)slot*BSD; };
    auto LSl = [&](int slot) { return lnl + (size_t)slot*BSD; };

    // ---- weight prep: 2 launches ----
    {
        WsAll wa;
        wa.src[0]=aWq; wa.src[1]=aWk; wa.src[2]=aWv; wa.src[3]=aGw; wa.src[4]=aOw;
        wa.th[0]=wqh; wa.th[1]=wkh; wa.th[2]=wvh; wa.th[3]=gwh; wa.th[4]=owh;
        wa.tl[0]=wql; wa.tl[1]=wkl; wa.tl[2]=wvl; wa.tl[3]=gwl; wa.tl[4]=owl;
        wa.aOb = aOb;
        wsplit_all<<<dim3(8, 8, 36), 256>>>(wa);
        wsplit_merged<<<dim3(64, 64, 12), 256>>>(ff_w1, ff_w2);
    }

    auto run_ln = [&](int nz, const float* xs[], const float* gbase, const float* bbase,
                      const int* ks, const int* slots) {
        LnBatch lb;
        for (int j = 0; j < nz; j++)
            lb.s[j] = { xs[j], gbase + (size_t)ks[j]*DD, bbase + (size_t)ks[j]*DD,
                        LS(slots[j]), LSl(slots[j]) };
        ln_kernel<<<dim3(MM/8, nz), 256>>>(lb);
    };

    auto run_qkvg = [&](int nz, const int* mods, const int* qslot, const int* kvslot) {
        Batch bt = {};
        for (int j = 0; j < nz; j++) {
            int k = mods[j];
            for (int c = 0; c < 4; c++) {
                Slice& s = bt.s[j*4 + c];
                int slot = (c == 0) ? qslot[j] : kvslot[j];
                s.Ah = LS(slot); s.Al = LSl(slot);
                const bf16* bh[4] = { wqh, wkh, wvh, gwh };
                const bf16* bl[4] = { wql, wkl, wvl, gwl };
                s.Bh = bh[c] + (size_t)k*DD*DD;
                s.Bl = bl[c] + (size_t)k*DD*DD;
                s.bias = (c == 3) ? (aGb + (size_t)k*DD) : nullptr;
                s.C = QKVG[c] + (size_t)j*BSD;
                s.mode = (c == 3) ? 2 : 0;
                s.lda = DD; s.ldb = DD; s.Ksub = DD;
            }
        }
        gemm_batched<<<dim3(DD/128, MM/128, nz*4), 256, GSMEM>>>(bt, MM, DD);
    };

    auto run_attn = [&](int nz) {
        AtBatch ab = {};
        for (int j = 0; j < nz; j++)
            ab.s[j] = { Qb + (size_t)j*BSD, Kb + (size_t)j*BSD, Vb + (size_t)j*BSD,
                        Gg + (size_t)j*BSD, cth + (size_t)j*BSD, ctl + (size_t)j*BSD };
        attn_core_kernel<<<dim3((BB*HH*SS*32)/256, nz), 256>>>(ab, mask);
    };

    // proj split-K x4: slice j*4+sp, Ksub 64
    auto run_proj_partials = [&](int nz, const int* mods) {
        Batch bt = {};
        for (int j = 0; j < nz; j++)
            for (int sp = 0; sp < 4; sp++) {
                Slice& s = bt.s[j*4 + sp];
                s.Ah = cth + (size_t)j*BSD + sp*64;
                s.Al = ctl + (size_t)j*BSD + sp*64;
                s.Bh = owh + (size_t)mods[j]*DD*DD + sp*64;
                s.Bl = owl + (size_t)mods[j]*DD*DD + sp*64;
                s.C = part + (size_t)(j*4 + sp)*MD;
                s.lda = DD; s.ldb = DD; s.Ksub = 64;
            }
        gemm_batched<<<dim3(DD/128, MM/128, nz*4), 256, GSMEM>>>(bt, MM, DD);
    };

    auto run_ff_gemms = [&](int nz, const int* mods, const int* lnslots, int nsp) {
        Batch b1 = {};
        for (int j = 0; j < nz; j++) {
            Slice& s = b1.s[j];
            s.Ah = LS(lnslots[j]); s.Al = LSl(lnslots[j]);
            s.Bh = w1h + (size_t)mods[j]*DD*HID; s.Bl = w1l + (size_t)mods[j]*DD*HID;
            s.bias = ff_b1 + (size_t)mods[j]*HID;
            s.Ch = hidh + (size_t)j*MH; s.Cl = hidl + (size_t)j*MH;
            s.mode = 1; s.lda = DD; s.ldb = DD; s.Ksub = DD;
        }
        gemm_batched<<<dim3(HID/128, MM/128, nz), 256, GSMEM>>>(b1, MM, HID);
        int ks = HID / nsp;
        Batch b2 = {};
        for (int j = 0; j < nz; j++)
            for (int sp = 0; sp < nsp; sp++) {
                Slice& s = b2.s[j*nsp + sp];
                s.Ah = hidh + (size_t)j*MH + sp*ks;
                s.Al = hidl + (size_t)j*MH + sp*ks;
                s.Bh = w2h + (size_t)mods[j]*HID*DD + sp*ks;
                s.Bl = w2l + (size_t)mods[j]*HID*DD + sp*ks;
                s.C = part + (size_t)(j*nsp + sp)*MD;
                s.lda = HID; s.ldb = HID; s.Ksub = ks;
            }
        gemm_batched<<<dim3(DD/128, MM/128, nz*nsp), 256, GSMEM>>>(b2, MM, DD);
    };

    // initial block-LNs: ln0->4, ln1->5, ln2->6
    {
        const float* xs[3] = { L, Nb, O };
        const int lnk[3] = { 0, 1, 2 };
        const int slots[3] = { 4, 5, 6 };
        run_ln(3, xs, ln_g, ln_b, lnk, slots);
    }

    for (int it = 0; it < NITER; it++) {
        // -------- Phase 1: self blocks --------
        {
            const int mods[3] = { 0, 1, 2 };
            const int slots[3] = { 4, 5, 6 };
            run_qkvg(3, mods, slots, slots);
            run_attn(3);
            run_proj_partials(3, mods);
            FRdBatch pr = {};
            for (int j = 0; j < 3; j++)
                pr.s[j] = { part + (size_t)j*4*MD, aOb + (size_t)mods[j]*DD, X[j], X[j], 4, 1,
                            ff_g + (size_t)mods[j]*DD, ff_b + (size_t)mods[j]*DD, LS(j), LSl(j),
                            nullptr, nullptr, nullptr, nullptr };
            fused_reduce_ln<<<dim3(MM/8, 3), 256>>>(pr);
            const int ffslots[3] = { 0, 1, 2 };
            run_ff_gemms(3, mods, ffslots, 8);
            FRdBatch rb = {};
            rb.s[0] = { part + 0*8*MD, ff_b2 + 0*DD, L, L, 8, 1,
                        ln_g + 4*DD, ln_b + 4*DD, LS(0), LSl(0),
                        nullptr, nullptr, nullptr, nullptr };
            rb.s[1] = { part + 1*8*MD, ff_b2 + 1*DD, Nb, Nb, 8, 1,
                        ln_g + 5*DD, ln_b + 5*DD, LS(1), LSl(1),
                        nullptr, nullptr, nullptr, nullptr };
            rb.s[2] = { part + 2*8*MD, ff_b2 + 2*DD, O, O, 8, 2,
                        ln_g + 3*DD, ln_b + 3*DD, LS(3), LSl(3),
                        ln_g + 8*DD, ln_b + 8*DD, LS(2), LSl(2) };
            fused_reduce_ln<<<dim3(MM/8, 3), 256>>>(rb);
        }
        // -------- Phase 2: cross blocks --------
        {
            const int mods[2] = { 3, 4 };
            const int qslot[2] = { 0, 1 };
            const int kvslot[2] = { 3, 3 };
            run_qkvg(2, mods, qslot, kvslot);
            run_attn(2);
            run_proj_partials(2, mods);
            float* dst[2] = { L, Nb };
            FRdBatch pr = {};
            for (int j = 0; j < 2; j++)
                pr.s[j] = { part + (size_t)j*4*MD, aOb + (size_t)mods[j]*DD, dst[j], dst[j], 4, 1,
                            ff_g + (size_t)mods[j]*DD, ff_b + (size_t)mods[j]*DD, LS(j), LSl(j),
                            nullptr, nullptr, nullptr, nullptr };
            fused_reduce_ln<<<dim3(MM/8, 2), 256>>>(pr);
            const int ffslots[2] = { 0, 1 };
            run_ff_gemms(2, mods, ffslots, 8);
            FRdBatch rb = {};
            rb.s[0] = { part + 0*8*MD, ff_b2 + 3*DD, L, L, 8, 2,
                        ln_g + 6*DD, ln_b + 6*DD, LS(0), LSl(0),
                        ln_g + 0*DD, ln_b + 0*DD, LS(4), LSl(4) };
            rb.s[1] = { part + 1*8*MD, ff_b2 + 4*DD, Nb, Nb, 8, 2,
                        ln_g + 7*DD, ln_b + 7*DD, LS(1), LSl(1),
                        ln_g + 1*DD, ln_b + 1*DD, LS(5), LSl(5) };
            fused_reduce_ln<<<dim3(MM/8, 2), 256>>>(rb);
        }
        // -------- Phase 3: O update --------
        {
            const int mods[2] = { 5, 6 };
            const int qslot[2] = { 2, 2 };
            const int kvslot[2] = { 1, 0 };
            run_qkvg(2, mods, qslot, kvslot);
            run_attn(2);
            // proj5 + proj6, each split-K x4: 8 partial slices
            Batch bp = {};
            for (int m = 0; m < 2; m++)
                for (int sp = 0; sp < 4; sp++) {
                    Slice& s = bp.s[m*4 + sp];
                    s.Ah = cth + (size_t)m*BSD + sp*64;
                    s.Al = ctl + (size_t)m*BSD + sp*64;
                    s.Bh = owh + (size_t)(5 + m)*DD*DD + sp*64;
                    s.Bl = owl + (size_t)(5 + m)*DD*DD + sp*64;
                    s.C = part + (size_t)(m*4 + sp)*MD;
                    s.lda = DD; s.ldb = DD; s.Ksub = 64;
                }
            gemm_batched<<<dim3(DD/128, MM/128, 8), 256, GSMEM>>>(bp, MM, DD);
            FRdBatch rp = {};
            rp.s[0] = { part, b56, O, O, 8, 1,
                        ff_g + 5*DD, ff_b + 5*DD, LS(0), LSl(0),
                        nullptr, nullptr, nullptr, nullptr };
            fused_reduce_ln<<<dim3(MM/8, 1), 256>>>(rp);
            const int ffm[1] = { 5 };
            const int ffslots[1] = { 0 };
            run_ff_gemms(1, ffm, ffslots, 16);
            FRdBatch rb = {};
            rb.s[0] = { part, ff_b2 + 5*DD, O, O, 16, 1,
                        ln_g + 2*DD, ln_b + 2*DD, LS(6), LSl(6),
                        nullptr, nullptr, nullptr, nullptr };
            fused_reduce_ln<<<dim3(MM/8, 1), 256>>>(rb);
        }
    }
}

// round 16
// speedup vs baseline: 1.0273x; 1.0273x over previous
#include <cuda_runtime.h>
#include <cuda_bf16.h>
#include <stdint.h>
#include <math.h>

#define BB 2
#define SS 1024
#define DD 256
#define HH 4
#define CC 64
#define WINSZ 10
#define NITER 2
#define MM 2048
#define HID 2048
#define BSD (BB*SS*DD)
#define MH ((size_t)MM*HID)
#define MD ((size_t)MM*DD)

typedef __nv_bfloat16 bf16;

// ---------------- scratch (device globals; no allocation) -------------------
__device__ float g_Q[3*BSD], g_Kb[3*BSD], g_Vb[3*BSD], g_Gb[3*BSD];
__device__ float g_b56[DD];
__device__ float g_part[24*MD];
__device__ bf16 g_lnh[7*BSD], g_lnl[7*BSD];
__device__ bf16 g_cth[3*BSD], g_ctl[3*BSD];
__device__ bf16 g_hidh[3*MH], g_hidl[3*MH];

__device__ bf16 g_WqTh[7*DD*DD], g_WqTl[7*DD*DD];
__device__ bf16 g_WkTh[7*DD*DD], g_WkTl[7*DD*DD];
__device__ bf16 g_WvTh[7*DD*DD], g_WvTl[7*DD*DD];
__device__ bf16 g_GwTh[7*DD*DD], g_GwTl[7*DD*DD];
__device__ bf16 g_OwTh[7*DD*DD], g_OwTl[7*DD*DD];
__device__ bf16 g_w1Th[(size_t)6*DD*HID], g_w1Tl[(size_t)6*DD*HID];
__device__ bf16 g_w2Th[(size_t)6*HID*DD], g_w2Tl[(size_t)6*HID*DD];

__device__ __forceinline__ void split2(float v, bf16& h, bf16& l){
    h = __float2bfloat16(v);
    l = __float2bfloat16(v - __bfloat162float(h));
}
__device__ __forceinline__ uint32_t smem_u32(const void* p){
    uint32_t a;
    asm("{ .reg .u64 t; cvta.to.shared.u64 t, %1; cvt.u32.u64 %0, t; }" : "=r"(a) : "l"(p));
    return a;
}
__device__ __forceinline__ void cp16(uint32_t saddr, const void* g){
    asm volatile("cp.async.cg.shared.global [%0], [%1], 16;" :: "r"(saddr), "l"(g));
}
__device__ __forceinline__ void ldsm_x4(uint32_t* r, uint32_t addr){
    asm volatile("ldmatrix.sync.aligned.m8n8.x4.shared.b16 {%0,%1,%2,%3}, [%4];"
        : "=r"(r[0]), "=r"(r[1]), "=r"(r[2]), "=r"(r[3]) : "r"(addr));
}
__device__ __forceinline__ float warp_sum(float s){
    #pragma unroll
    for (int o = 16; o > 0; o >>= 1) s += __shfl_xor_sync(0xffffffffu, s, o);
    return s;
}
__device__ __forceinline__ void store8(bf16* oh, bf16* ol, size_t base, const float* v){
    __align__(16) bf16 h[8], l[8];
    #pragma unroll
    for (int i = 0; i < 8; i++) split2(v[i], h[i], l[i]);
    *(uint4*)&oh[base] = *(const uint4*)h;
    *(uint4*)&ol[base] = *(const uint4*)l;
}

// ---------------- weight transpose + split ----------------------------------
__device__ __forceinline__ void wsplit_body(
    const float* w, bf16* th, bf16* tl, int N, int ldt)
{
    __shared__ float sm[32][33];
    int n0 = blockIdx.x * 32, k0 = blockIdx.y * 32;
    int tx = threadIdx.x & 31, ty = threadIdx.x >> 5;
    #pragma unroll
    for (int i = 0; i < 4; i++)
        sm[ty + i*8][tx] = w[(size_t)(k0 + ty + i*8) * N + n0 + tx];
    __syncthreads();
    #pragma unroll
    for (int i = 0; i < 4; i++) {
        int n = n0 + ty + i*8;
        bf16 h, l; split2(sm[tx][ty + i*8], h, l);
        th[(size_t)n * ldt + k0 + tx] = h;
        tl[(size_t)n * ldt + k0 + tx] = l;
    }
}

struct WsAll { const float* src[5]; bf16* th[5]; bf16* tl[5]; const float* aOb; };
__global__ void __launch_bounds__(256) wsplit_all(WsAll wa)
{
    if (blockIdx.z == 35) {
        if (blockIdx.x == 0 && blockIdx.y == 0 && threadIdx.x < DD)
            g_b56[threadIdx.x] = wa.aOb[5*DD + threadIdx.x] + wa.aOb[6*DD + threadIdx.x];
        return;
    }
    int fam = blockIdx.z / 7, mod = blockIdx.z % 7;
    wsplit_body(wa.src[fam] + (size_t)mod*DD*DD,
                wa.th[fam] + (size_t)mod*DD*DD, wa.tl[fam] + (size_t)mod*DD*DD,
                DD, DD);
}
__global__ void __launch_bounds__(256) wsplit_merged(
    const float* __restrict__ W1, const float* __restrict__ W2)
{
    int z = blockIdx.z;
    if (z < 6) {
        if (blockIdx.y >= 8) return;
        wsplit_body(W1 + (size_t)z*DD*HID,
                    g_w1Th + (size_t)z*DD*HID, g_w1Tl + (size_t)z*DD*HID,
                    HID, DD);
    } else {
        if (blockIdx.x >= 8) return;
        int m = z - 6;
        wsplit_body(W2 + (size_t)m*HID*DD,
                    g_w2Th + (size_t)m*HID*DD, g_w2Tl + (size_t)m*HID*DD,
                    DD, HID);
    }
}

// ---------------- warp-per-row LayerNorm (batched over z) -------------------
struct LnS { const float* x; const float* g; const float* b; bf16* oh; bf16* ol; };
struct LnBatch { LnS s[3]; };

__global__ void __launch_bounds__(256) ln_kernel(LnBatch lb)
{
    LnS sl = lb.s[blockIdx.y];
    int wid = threadIdx.x >> 5, lane = threadIdx.x & 31;
    int row = blockIdx.x * 8 + wid;
    size_t base = (size_t)row * DD + lane * 8;

    float v[8];
    float4 p0 = *(const float4*)&sl.x[base];
    float4 p1 = *(const float4*)&sl.x[base + 4];
    v[0]=p0.x; v[1]=p0.y; v[2]=p0.z; v[3]=p0.w;
    v[4]=p1.x; v[5]=p1.y; v[6]=p1.z; v[7]=p1.w;

    float s = 0.f;
    #pragma unroll
    for (int i = 0; i < 8; i++) s += v[i];
    float mean = warp_sum(s) * (1.0f/DD);
    float q = 0.f;
    #pragma unroll
    for (int i = 0; i < 8; i++) { float d = v[i]-mean; q += d*d; }
    float rstd = rsqrtf(warp_sum(q) * (1.0f/DD) + 1e-5f);

    int c = lane * 8;
    float4 g0 = *(const float4*)&sl.g[c], g1 = *(const float4*)&sl.g[c+4];
    float4 b0 = *(const float4*)&sl.b[c], b1 = *(const float4*)&sl.b[c+4];
    float gg[8] = {g0.x,g0.y,g0.z,g0.w,g1.x,g1.y,g1.z,g1.w};
    float bb[8] = {b0.x,b0.y,b0.z,b0.w,b1.x,b1.y,b1.z,b1.w};
    float out[8];
    #pragma unroll
    for (int i = 0; i < 8; i++) out[i] = (v[i]-mean)*rstd*gg[i] + bb[i];
    store8(sl.oh, sl.ol, base, out);
}

// ---------------- fused split-K reduce + LN(s), warp-per-row ----------------
struct FRdS {
    const float* p; const float* bias; const float* res; float* dst; int nsplit;
    int nln;
    const float *lg0, *lb0; bf16 *oh0, *ol0;
    const float *lg1, *lb1; bf16 *oh1, *ol1;
};
struct FRdBatch { FRdS s[3]; };

__global__ void __launch_bounds__(256) fused_reduce_ln(FRdBatch rb)
{
    FRdS sl = rb.s[blockIdx.y];
    int wid = threadIdx.x >> 5, lane = threadIdx.x & 31;
    int row = blockIdx.x * 8 + wid;
    size_t base = (size_t)row * DD + lane * 8;
    int c = lane * 8;

    float a[8];
    {
        float4 p0 = *(const float4*)&sl.p[base];
        float4 p1 = *(const float4*)&sl.p[base + 4];
        a[0]=p0.x; a[1]=p0.y; a[2]=p0.z; a[3]=p0.w;
        a[4]=p1.x; a[5]=p1.y; a[6]=p1.z; a[7]=p1.w;
    }
    for (int s = 1; s < sl.nsplit; s++) {
        float4 p0 = *(const float4*)&sl.p[(size_t)s*MD + base];
        float4 p1 = *(const float4*)&sl.p[(size_t)s*MD + base + 4];
        a[0]+=p0.x; a[1]+=p0.y; a[2]+=p0.z; a[3]+=p0.w;
        a[4]+=p1.x; a[5]+=p1.y; a[6]+=p1.z; a[7]+=p1.w;
    }
    {
        float4 b0 = *(const float4*)&sl.bias[c], b1 = *(const float4*)&sl.bias[c+4];
        a[0]+=b0.x; a[1]+=b0.y; a[2]+=b0.z; a[3]+=b0.w;
        a[4]+=b1.x; a[5]+=b1.y; a[6]+=b1.z; a[7]+=b1.w;
    }
    if (sl.res) {
        float4 r0 = *(const float4*)&sl.res[base], r1 = *(const float4*)&sl.res[base+4];
        a[0]+=r0.x; a[1]+=r0.y; a[2]+=r0.z; a[3]+=r0.w;
        a[4]+=r1.x; a[5]+=r1.y; a[6]+=r1.z; a[7]+=r1.w;
    }
    {
        float4 o0 = make_float4(a[0],a[1],a[2],a[3]);
        float4 o1 = make_float4(a[4],a[5],a[6],a[7]);
        *(float4*)&sl.dst[base] = o0;
        *(float4*)&sl.dst[base+4] = o1;
    }

    float s = 0.f;
    #pragma unroll
    for (int i = 0; i < 8; i++) s += a[i];
    float mean = warp_sum(s) * (1.0f/DD);
    float q = 0.f;
    #pragma unroll
    for (int i = 0; i < 8; i++) { float d = a[i]-mean; q += d*d; }
    float rstd = rsqrtf(warp_sum(q) * (1.0f/DD) + 1e-5f);

    float nrm[8];
    #pragma unroll
    for (int i = 0; i < 8; i++) nrm[i] = (a[i]-mean)*rstd;

    {
        float4 g0 = *(const float4*)&sl.lg0[c], g1 = *(const float4*)&sl.lg0[c+4];
        float4 b0 = *(const float4*)&sl.lb0[c], b1 = *(const float4*)&sl.lb0[c+4];
        float gg[8] = {g0.x,g0.y,g0.z,g0.w,g1.x,g1.y,g1.z,g1.w};
        float bb[8] = {b0.x,b0.y,b0.z,b0.w,b1.x,b1.y,b1.z,b1.w};
        float out[8];
        #pragma unroll
        for (int i = 0; i < 8; i++) out[i] = nrm[i]*gg[i] + bb[i];
        store8(sl.oh0, sl.ol0, base, out);
    }
    if (sl.nln > 1) {
        float4 g0 = *(const float4*)&sl.lg1[c], g1 = *(const float4*)&sl.lg1[c+4];
        float4 b0 = *(const float4*)&sl.lb1[c], b1 = *(const float4*)&sl.lb1[c+4];
        float gg[8] = {g0.x,g0.y,g0.z,g0.w,g1.x,g1.y,g1.z,g1.w};
        float bb[8] = {b0.x,b0.y,b0.z,b0.w,b1.x,b1.y,b1.z,b1.w};
        float out[8];
        #pragma unroll
        for (int i = 0; i < 8; i++) out[i] = nrm[i]*gg[i] + bb[i];
        store8(sl.oh1, sl.ol1, base, out);
    }
}

// ---------------- batched split-compensated MMA GEMM (128x64 tile) ----------
struct Slice {
    const bf16 *Ah, *Al, *Bh, *Bl;
    const float *bias, *res;
    float* C; bf16 *Ch, *Cl;
    int mode, lda, ldb, Ksub;
};
struct Batch { Slice s[12]; };

#define BKC 32
#define LDSB 40
#define AROWS 128
#define BROWS 64
#define A_ARR (AROWS*LDSB)
#define B_ARR (BROWS*LDSB)
#define STGE (2*A_ARR + 2*B_ARR)
#define GSMEM (2*STGE*2)

__device__ __forceinline__ void mma16816(float* c, const uint32_t* a, const uint32_t* b){
    asm volatile("mma.sync.aligned.m16n8k16.row.col.f32.bf16.bf16.f32 "
        "{%0,%1,%2,%3}, {%4,%5,%6,%7}, {%8,%9}, {%0,%1,%2,%3};"
        : "+f"(c[0]), "+f"(c[1]), "+f"(c[2]), "+f"(c[3])
        : "r"(a[0]), "r"(a[1]), "r"(a[2]), "r"(a[3]), "r"(b[0]), "r"(b[1]));
}

__global__ void __launch_bounds__(256,3)
gemm_batched(Batch bt, int M, int N)
{
    extern __shared__ __align__(16) bf16 smem[];
    const Slice sl = bt.s[blockIdx.z];
    const int tid  = threadIdx.x;
    const int warp = tid >> 5, lane = tid & 31;
    const int wm = warp >> 1, wn = warp & 1;          // 4 x 2 warps, 32x32 tiles
    const int row0 = blockIdx.y * 128, col0 = blockIdx.x * 64;
    const int g8 = lane >> 2, tig = lane & 3;
    const uint32_t sb = smem_u32(smem);
    const int NC = sl.Ksub / BKC;
    const int lda = sl.lda, ldb = sl.ldb;

    float acc[2][4][4];
    #pragma unroll
    for (int i=0;i<2;i++) for (int j=0;j<4;j++) for (int q=0;q<4;q++) acc[i][j][q]=0.f;

    // A: 512 chunks/array -> 2 per thread; B: 256 chunks/array -> 1 per thread
    const int rA0 = tid >> 2,  cA0 = (tid & 3) * 8;
    const int rA1 = rA0 + 64;
    const int rB  = tid >> 2,  cB  = (tid & 3) * 8;   // rB < 64

    const int lmat = lane >> 3, lrow = lane & 7;
    const uint32_t a_lane_off = (uint32_t)(((lmat & 1) * 8 + lrow) * LDSB + (lmat >> 1) * 8) * 2;
    const uint32_t b_lane_off = (uint32_t)(((lmat >> 1) * 8 + lrow) * LDSB + (lmat & 1) * 8) * 2;

    auto cpStage = [&](int c, int st){
        int kc = c * BKC;
        uint32_t base = sb + (uint32_t)(st * STGE) * 2;
        uint32_t soA0 = (uint32_t)(rA0 * LDSB + cA0) * 2;
        uint32_t soA1 = (uint32_t)(rA1 * LDSB + cA0) * 2;
        uint32_t soB  = (uint32_t)(rB  * LDSB + cB ) * 2;
        cp16(base + soA0,              sl.Ah + (size_t)(row0 + rA0) * lda + kc + cA0);
        cp16(base + soA1,              sl.Ah + (size_t)(row0 + rA1) * lda + kc + cA0);
        cp16(base + A_ARR*2 + soA0,    sl.Al + (size_t)(row0 + rA0) * lda + kc + cA0);
        cp16(base + A_ARR*2 + soA1,    sl.Al + (size_t)(row0 + rA1) * lda + kc + cA0);
        cp16(base + A_ARR*4 + soB,             sl.Bh + (size_t)(col0 + rB) * ldb + kc + cB);
        cp16(base + A_ARR*4 + B_ARR*2 + soB,   sl.Bl + (size_t)(col0 + rB) * ldb + kc + cB);
        asm volatile("cp.async.commit_group;" ::: "memory");
    };

    cpStage(0, 0);
    if (NC > 1) cpStage(1, 1);
    else asm volatile("cp.async.commit_group;" ::: "memory");

    for (int c = 0; c < NC; c++) {
        const int st = c & 1;
        if (c + 2 < NC) asm volatile("cp.async.wait_group 1;" ::: "memory");
        else            asm volatile("cp.async.wait_group 0;" ::: "memory");
        __syncthreads();

        const uint32_t sA_h = sb + (uint32_t)(st*STGE) * 2;
        const uint32_t sA_l = sA_h + A_ARR*2;
        const uint32_t sB_h = sA_h + A_ARR*4;
        const uint32_t sB_l = sB_h + B_ARR*2;

        #pragma unroll
        for (int kk = 0; kk < 2; kk++) {
            const uint32_t kbo = (uint32_t)(kk * 16) * 2;
            uint32_t bh[4][2], bl[4][2];
            #pragma unroll
            for (int pr = 0; pr < 2; pr++) {
                uint32_t nbase = (uint32_t)((wn*32 + pr*16) * LDSB) * 2;
                uint32_t r4[4];
                ldsm_x4(r4, sB_h + nbase + kbo + b_lane_off);
                bh[pr*2][0] = r4[0]; bh[pr*2][1] = r4[1];
                bh[pr*2+1][0] = r4[2]; bh[pr*2+1][1] = r4[3];
                ldsm_x4(r4, sB_l + nbase + kbo + b_lane_off);
                bl[pr*2][0] = r4[0]; bl[pr*2][1] = r4[1];
                bl[pr*2+1][0] = r4[2]; bl[pr*2+1][1] = r4[3];
            }
            #pragma unroll
            for (int mi = 0; mi < 2; mi++) {
                uint32_t rbase = (uint32_t)((wm*32 + mi*16) * LDSB) * 2;
                uint32_t ah[4], al[4];
                ldsm_x4(ah, sA_h + rbase + kbo + a_lane_off);
                ldsm_x4(al, sA_l + rbase + kbo + a_lane_off);
                #pragma unroll
                for (int ni = 0; ni < 4; ni++) {
                    mma16816(acc[mi][ni], ah, bh[ni]);
                    mma16816(acc[mi][ni], ah, bl[ni]);
                    mma16816(acc[mi][ni], al, bh[ni]);
                }
            }
        }
        __syncthreads();
        if (c + 2 < NC) cpStage(c + 2, st);
    }

    #pragma unroll
    for (int mi = 0; mi < 2; mi++) {
        #pragma unroll
        for (int ni = 0; ni < 4; ni++) {
            int r1 = row0 + wm*32 + mi*16 + g8;
            int c1 = col0 + wn*32 + ni*8 + tig*2;
            #pragma unroll
            for (int q = 0; q < 4; q++) {
                int r = (q < 2) ? r1 : r1 + 8;
                int cc = c1 + (q & 1);
                float v = acc[mi][ni][q];
                if (sl.bias) v += sl.bias[cc];
                if (sl.mode == 1)      v = fmaxf(v, 0.f);
                else if (sl.mode == 2) v = 1.f / (1.f + __expf(-v));
                if (sl.Ch) {
                    bf16 h, l; split2(v, h, l);
                    sl.Ch[(size_t)r * N + cc] = h;
                    sl.Cl[(size_t)r * N + cc] = l;
                } else {
                    if (sl.res) v += sl.res[(size_t)r * N + cc];
                    sl.C[(size_t)r * N + cc] = v;
                }
            }
        }
    }
}

// ---------------- windowed attention core (batched over z) ------------------
struct AtS { const float* Q; const float* K; const float* V; const float* G;
             bf16* cth; bf16* ctl; };
struct AtBatch { AtS s[3]; };

__global__ void __launch_bounds__(256)
attn_core_kernel(AtBatch ab, const unsigned char* __restrict__ mask)
{
    AtS sl = ab.s[blockIdx.y];
    int idx  = blockIdx.x * blockDim.x + threadIdx.x;
    int gw   = idx >> 5;
    int lane = idx & 31;
    int s = gw & (SS - 1);
    int h = (gw >> 10) & (HH - 1);
    int n = gw >> 12;

    int base_q = (n * SS + s) * DD + h * CC;
    float q0 = sl.Q[base_q + lane];
    float q1 = sl.Q[base_q + 32 + lane];

    int t0 = s - WINSZ; if (t0 < 0) t0 = 0;
    int t1 = s + WINSZ; if (t1 > SS - 1) t1 = SS - 1;
    int cnt = t1 - t0 + 1;

    float sc[2 * WINSZ + 1];
    float mx = -1e30f;
    for (int i = 0; i < cnt; i++) {
        int t = t0 + i;
        float v;
        if (mask[n * SS + t]) v = -1e30f;
        else {
            int bk = (n * SS + t) * DD + h * CC;
            float p = q0 * sl.K[bk + lane] + q1 * sl.K[bk + 32 + lane];
            #pragma unroll
            for (int o = 16; o > 0; o >>= 1) p += __shfl_xor_sync(0xffffffffu, p, o);
            v = p * 0.125f;
        }
        sc[i] = v;
        mx = fmaxf(mx, v);
    }
    float denom = 0.f;
    for (int i = 0; i < cnt; i++) {
        float e = (sc[i] <= -1e29f) ? 0.f : __expf(sc[i] - mx);
        sc[i] = e; denom += e;
    }
    float inv = (denom > 0.f) ? (1.f / denom) : 0.f;
    float o0 = 0.f, o1 = 0.f;
    for (int i = 0; i < cnt; i++) {
        int bv = (n * SS + (t0 + i)) * DD + h * CC;
        float a = sc[i] * inv;
        o0 = fmaf(a, sl.V[bv + lane], o0);
        o1 = fmaf(a, sl.V[bv + 32 + lane], o1);
    }
    float v0 = o0 * sl.G[base_q + lane];
    float v1 = o1 * sl.G[base_q + 32 + lane];
    bf16 h0, l0, h1, l1;
    split2(v0, h0, l0); split2(v1, h1, l1);
    sl.cth[base_q + lane]      = h0;  sl.ctl[base_q + lane]      = l0;
    sl.cth[base_q + 32 + lane] = h1;  sl.ctl[base_q + 32 + lane] = l1;
}

// ---------------- host orchestration ----------------------------------------
extern "C" void kernel_launch(void* const* d_in, const int* in_sizes, int n_in,
                              void* d_out, int out_size)
{
    (void)in_sizes; (void)n_in; (void)out_size;
    const float* inL = (const float*)d_in[0];
    const float* inN = (const float*)d_in[1];
    const float* inO = (const float*)d_in[2];
    const unsigned char* mask = (const unsigned char*)d_in[3];
    const float* aWq = (const float*)d_in[4];
    const float* aWk = (const float*)d_in[5];
    const float* aWv = (const float*)d_in[6];
    const float* aGw = (const float*)d_in[7];
    const float* aGb = (const float*)d_in[8];
    const float* aOw = (const float*)d_in[9];
    const float* aOb = (const float*)d_in[10];
    const float* ln_g = (const float*)d_in[11];
    const float* ln_b = (const float*)d_in[12];
    const float* ff_g = (const float*)d_in[13];
    const float* ff_b = (const float*)d_in[14];
    const float* ff_w1 = (const float*)d_in[15];
    const float* ff_b1 = (const float*)d_in[16];
    const float* ff_w2 = (const float*)d_in[17];
    const float* ff_b2 = (const float*)d_in[18];

    float* L  = (float*)d_out;
    float* Nb = L + BSD;
    float* O  = Nb + BSD;
    float* X[3] = { L, Nb, O };

    cudaMemcpyAsync(L,  inL, (size_t)BSD * sizeof(float), cudaMemcpyDeviceToDevice);
    cudaMemcpyAsync(Nb, inN, (size_t)BSD * sizeof(float), cudaMemcpyDeviceToDevice);
    cudaMemcpyAsync(O,  inO, (size_t)BSD * sizeof(float), cudaMemcpyDeviceToDevice);

    void* pa;
    #define SYM(var, sym) cudaGetSymbolAddress(&pa, sym); auto var = (decltype(&sym[0]))pa;
    SYM(Qb, g_Q) SYM(Kb, g_Kb) SYM(Vb, g_Vb) SYM(Gg, g_Gb)
    SYM(lnh, g_lnh) SYM(lnl, g_lnl)
    SYM(cth, g_cth) SYM(ctl, g_ctl)
    SYM(hidh, g_hidh) SYM(hidl, g_hidl)
    SYM(b56, g_b56) SYM(part, g_part)
    SYM(wqh, g_WqTh) SYM(wql, g_WqTl) SYM(wkh, g_WkTh) SYM(wkl, g_WkTl)
    SYM(wvh, g_WvTh) SYM(wvl, g_WvTl) SYM(gwh, g_GwTh) SYM(gwl, g_GwTl)
    SYM(owh, g_OwTh) SYM(owl, g_OwTl)
    SYM(w1h, g_w1Th) SYM(w1l, g_w1Tl) SYM(w2h, g_w2Th) SYM(w2l, g_w2Tl)
    #undef SYM

    cudaFuncSetAttribute(gemm_batched, cudaFuncAttributeMaxDynamicSharedMemorySize, GSMEM);

    float* QKVG[4] = { Qb, Kb, Vb, Gg };
    auto LS = [&](int slot) { return lnh + (size_t)slot*BSD; };
    auto LSl = [&](int slot) { return lnl + (size_t)slot*BSD; };

    // ---- weight prep: 2 launches ----
    {
        WsAll wa;
        wa.src[0]=aWq; wa.src[1]=aWk; wa.src[2]=aWv; wa.src[3]=aGw; wa.src[4]=aOw;
        wa.th[0]=wqh; wa.th[1]=wkh; wa.th[2]=wvh; wa.th[3]=gwh; wa.th[4]=owh;
        wa.tl[0]=wql; wa.tl[1]=wkl; wa.tl[2]=wvl; wa.tl[3]=gwl; wa.tl[4]=owl;
        wa.aOb = aOb;
        wsplit_all<<<dim3(8, 8, 36), 256>>>(wa);
        wsplit_merged<<<dim3(64, 64, 12), 256>>>(ff_w1, ff_w2);
    }

    auto run_ln = [&](int nz, const float* xs[], const float* gbase, const float* bbase,
                      const int* ks, const int* slots) {
        LnBatch lb;
        for (int j = 0; j < nz; j++)
            lb.s[j] = { xs[j], gbase + (size_t)ks[j]*DD, bbase + (size_t)ks[j]*DD,
                        LS(slots[j]), LSl(slots[j]) };
        ln_kernel<<<dim3(MM/8, nz), 256>>>(lb);
    };

    auto run_qkvg = [&](int nz, const int* mods, const int* qslot, const int* kvslot) {
        Batch bt = {};
        for (int j = 0; j < nz; j++) {
            int k = mods[j];
            for (int c = 0; c < 4; c++) {
                Slice& s = bt.s[j*4 + c];
                int slot = (c == 0) ? qslot[j] : kvslot[j];
                s.Ah = LS(slot); s.Al = LSl(slot);
                const bf16* bh[4] = { wqh, wkh, wvh, gwh };
                const bf16* bl[4] = { wql, wkl, wvl, gwl };
                s.Bh = bh[c] + (size_t)k*DD*DD;
                s.Bl = bl[c] + (size_t)k*DD*DD;
                s.bias = (c == 3) ? (aGb + (size_t)k*DD) : nullptr;
                s.C = QKVG[c] + (size_t)j*BSD;
                s.mode = (c == 3) ? 2 : 0;
                s.lda = DD; s.ldb = DD; s.Ksub = DD;
            }
        }
        gemm_batched<<<dim3(DD/64, MM/128, nz*4), 256, GSMEM>>>(bt, MM, DD);
    };

    auto run_attn = [&](int nz) {
        AtBatch ab = {};
        for (int j = 0; j < nz; j++)
            ab.s[j] = { Qb + (size_t)j*BSD, Kb + (size_t)j*BSD, Vb + (size_t)j*BSD,
                        Gg + (size_t)j*BSD, cth + (size_t)j*BSD, ctl + (size_t)j*BSD };
        attn_core_kernel<<<dim3((BB*HH*SS*32)/256, nz), 256>>>(ab, mask);
    };

    // proj split-K x2 (Ksub 128)
    auto run_proj_partials = [&](int nz, const int* mods) {
        Batch bt = {};
        for (int j = 0; j < nz; j++)
            for (int sp = 0; sp < 2; sp++) {
                Slice& s = bt.s[j*2 + sp];
                s.Ah = cth + (size_t)j*BSD + sp*128;
                s.Al = ctl + (size_t)j*BSD + sp*128;
                s.Bh = owh + (size_t)mods[j]*DD*DD + sp*128;
                s.Bl = owl + (size_t)mods[j]*DD*DD + sp*128;
                s.C = part + (size_t)(j*2 + sp)*MD;
                s.lda = DD; s.ldb = DD; s.Ksub = 128;
            }
        gemm_batched<<<dim3(DD/64, MM/128, nz*2), 256, GSMEM>>>(bt, MM, DD);
    };

    auto run_ff_gemms = [&](int nz, const int* mods, const int* lnslots) {
        Batch b1 = {};
        for (int j = 0; j < nz; j++) {
            Slice& s = b1.s[j];
            s.Ah = LS(lnslots[j]); s.Al = LSl(lnslots[j]);
            s.Bh = w1h + (size_t)mods[j]*DD*HID; s.Bl = w1l + (size_t)mods[j]*DD*HID;
            s.bias = ff_b1 + (size_t)mods[j]*HID;
            s.Ch = hidh + (size_t)j*MH; s.Cl = hidl + (size_t)j*MH;
            s.mode = 1; s.lda = DD; s.ldb = DD; s.Ksub = DD;
        }
        gemm_batched<<<dim3(HID/64, MM/128, nz), 256, GSMEM>>>(b1, MM, HID);
        Batch b2 = {};
        for (int j = 0; j < nz; j++)
            for (int sp = 0; sp < 4; sp++) {
                Slice& s = b2.s[j*4 + sp];
                s.Ah = hidh + (size_t)j*MH + sp*512;
                s.Al = hidl + (size_t)j*MH + sp*512;
                s.Bh = w2h + (size_t)mods[j]*HID*DD + sp*512;
                s.Bl = w2l + (size_t)mods[j]*HID*DD + sp*512;
                s.C = part + (size_t)(j*4 + sp)*MD;
                s.lda = HID; s.ldb = HID; s.Ksub = 512;
            }
        gemm_batched<<<dim3(DD/64, MM/128, nz*4), 256, GSMEM>>>(b2, MM, DD);
    };

    // initial block-LNs: ln0->4, ln1->5, ln2->6
    {
        const float* xs[3] = { L, Nb, O };
        const int lnk[3] = { 0, 1, 2 };
        const int slots[3] = { 4, 5, 6 };
        run_ln(3, xs, ln_g, ln_b, lnk, slots);
    }

    for (int it = 0; it < NITER; it++) {
        // -------- Phase 1: self blocks --------
        {
            const int mods[3] = { 0, 1, 2 };
            const int slots[3] = { 4, 5, 6 };
            run_qkvg(3, mods, slots, slots);
            run_attn(3);
            run_proj_partials(3, mods);
            FRdBatch pr = {};
            for (int j = 0; j < 3; j++)
                pr.s[j] = { part + (size_t)j*2*MD, aOb + (size_t)mods[j]*DD, X[j], X[j], 2, 1,
                            ff_g + (size_t)mods[j]*DD, ff_b + (size_t)mods[j]*DD, LS(j), LSl(j),
                            nullptr, nullptr, nullptr, nullptr };
            fused_reduce_ln<<<dim3(MM/8, 3), 256>>>(pr);
            const int ffslots[3] = { 0, 1, 2 };
            run_ff_gemms(3, mods, ffslots);
            FRdBatch rb = {};
            rb.s[0] = { part + 0*4*MD, ff_b2 + 0*DD, L, L, 4, 1,
                        ln_g + 4*DD, ln_b + 4*DD, LS(0), LSl(0),
                        nullptr, nullptr, nullptr, nullptr };
            rb.s[1] = { part + 1*4*MD, ff_b2 + 1*DD, Nb, Nb, 4, 1,
                        ln_g + 5*DD, ln_b + 5*DD, LS(1), LSl(1),
                        nullptr, nullptr, nullptr, nullptr };
            rb.s[2] = { part + 2*4*MD, ff_b2 + 2*DD, O, O, 4, 2,
                        ln_g + 3*DD, ln_b + 3*DD, LS(3), LSl(3),
                        ln_g + 8*DD, ln_b + 8*DD, LS(2), LSl(2) };
            fused_reduce_ln<<<dim3(MM/8, 3), 256>>>(rb);
        }
        // -------- Phase 2: cross blocks --------
        {
            const int mods[2] = { 3, 4 };
            const int qslot[2] = { 0, 1 };
            const int kvslot[2] = { 3, 3 };
            run_qkvg(2, mods, qslot, kvslot);
            run_attn(2);
            run_proj_partials(2, mods);
            float* dst[2] = { L, Nb };
            FRdBatch pr = {};
            for (int j = 0; j < 2; j++)
                pr.s[j] = { part + (size_t)j*2*MD, aOb + (size_t)mods[j]*DD, dst[j], dst[j], 2, 1,
                            ff_g + (size_t)mods[j]*DD, ff_b + (size_t)mods[j]*DD, LS(j), LSl(j),
                            nullptr, nullptr, nullptr, nullptr };
            fused_reduce_ln<<<dim3(MM/8, 2), 256>>>(pr);
            const int ffslots[2] = { 0, 1 };
            run_ff_gemms(2, mods, ffslots);
            FRdBatch rb = {};
            rb.s[0] = { part + 0*4*MD, ff_b2 + 3*DD, L, L, 4, 2,
                        ln_g + 6*DD, ln_b + 6*DD, LS(0), LSl(0),
                        ln_g + 0*DD, ln_b + 0*DD, LS(4), LSl(4) };
            rb.s[1] = { part + 1*4*MD, ff_b2 + 4*DD, Nb, Nb, 4, 2,
                        ln_g + 7*DD, ln_b + 7*DD, LS(1), LSl(1),
                        ln_g + 1*DD, ln_b + 1*DD, LS(5), LSl(5) };
            fused_reduce_ln<<<dim3(MM/8, 2), 256>>>(rb);
        }
        // -------- Phase 3: O update --------
        {
            const int mods[2] = { 5, 6 };
            const int qslot[2] = { 2, 2 };
            const int kvslot[2] = { 1, 0 };
            run_qkvg(2, mods, qslot, kvslot);
            run_attn(2);
            // proj5 + proj6, each split-K x2: 4 partial slices
            Batch bp = {};
            for (int m = 0; m < 2; m++)
                for (int sp = 0; sp < 2; sp++) {
                    Slice& s = bp.s[m*2 + sp];
                    s.Ah = cth + (size_t)m*BSD + sp*128;
                    s.Al = ctl + (size_t)m*BSD + sp*128;
                    s.Bh = owh + (size_t)(5 + m)*DD*DD + sp*128;
                    s.Bl = owl + (size_t)(5 + m)*DD*DD + sp*128;
                    s.C = part + (size_t)(m*2 + sp)*MD;
                    s.lda = DD; s.ldb = DD; s.Ksub = 128;
                }
            gemm_batched<<<dim3(DD/64, MM/128, 4), 256, GSMEM>>>(bp, MM, DD);
            FRdBatch rp = {};
            rp.s[0] = { part, b56, O, O, 4, 1,
                        ff_g + 5*DD, ff_b + 5*DD, LS(0), LSl(0),
                        nullptr, nullptr, nullptr, nullptr };
            fused_reduce_ln<<<dim3(MM/8, 1), 256>>>(rp);
            const int ffm[1] = { 5 };
            const int ffslots[1] = { 0 };
            run_ff_gemms(1, ffm, ffslots);
            FRdBatch rb = {};
            rb.s[0] = { part, ff_b2 + 5*DD, O, O, 4, 1,
                        ln_g + 2*DD, ln_b + 2*DD, LS(6), LSl(6),
                        nullptr, nullptr, nullptr, nullptr };
            fused_reduce_ln<<<dim3(MM/8, 1), 256>>>(rb);
        }
    }
}